// round 4
// baseline (speedup 1.0000x reference)
#include <cuda_runtime.h>
#include <cuda_bf16.h>
#include <cstdint>

// Problem constants
#define NNODES 50000
#define NEDGES 800000
#define FIN    128
#define HID    256
#define NGRAPH 128

// ---------------------------------------------------------------------------
// Scratch (static __device__ arrays; no allocation allowed)
// ---------------------------------------------------------------------------
__device__ float d_AX[(size_t)NNODES * FIN];       // A @ X            [N,128]
__device__ float d_H1[(size_t)NNODES * HID];       // relu(AX@W1+b1)   [N,256]
__device__ float d_T2[(size_t)NNODES * HID];       // H1 @ W2          [N,256]
__device__ int   d_deg[NNODES];
__device__ int   d_rptr[NNODES + 1];
__device__ int   d_cursor[NNODES];
__device__ int   d_csrc[NEDGES];
__device__ float d_csrw[NEDGES];
__device__ float d_G[NGRAPH * HID];                // pooled graph features

// ---------------------------------------------------------------------------
// 0. zero deg + G
// ---------------------------------------------------------------------------
__global__ void zero_kernel(int* deg, float* G) {
    int i = blockIdx.x * blockDim.x + threadIdx.x;
    if (i < NNODES) deg[i] = 0;
    if (i < NGRAPH * HID) G[i] = 0.0f;
}

// ---------------------------------------------------------------------------
// 1. degree histogram over edge_dst
// ---------------------------------------------------------------------------
__global__ void hist_kernel(const int* __restrict__ dst, int* __restrict__ deg) {
    int e = blockIdx.x * blockDim.x + threadIdx.x;
    if (e < NEDGES) atomicAdd(&deg[dst[e]], 1);
}

// ---------------------------------------------------------------------------
// 2. single-block exclusive scan (shuffle-based), also seeds cursor
// ---------------------------------------------------------------------------
__global__ void scan_kernel(const int* __restrict__ deg, int* __restrict__ rptr,
                            int* __restrict__ cursor) {
    __shared__ int wsum[32];
    __shared__ int chunk_total;
    const int t = threadIdx.x, lane = t & 31, wid = t >> 5;
    int carry = 0;
    for (int base = 0; base < NNODES; base += 1024) {
        int i = base + t;
        int v = (i < NNODES) ? deg[i] : 0;
        int x = v;
        #pragma unroll
        for (int off = 1; off < 32; off <<= 1) {
            int y = __shfl_up_sync(0xffffffffu, x, off);
            if (lane >= off) x += y;
        }
        if (lane == 31) wsum[wid] = x;
        __syncthreads();
        if (wid == 0) {
            int s = wsum[lane];
            #pragma unroll
            for (int off = 1; off < 32; off <<= 1) {
                int y = __shfl_up_sync(0xffffffffu, s, off);
                if (lane >= off) s += y;
            }
            wsum[lane] = s;
            if (lane == 31) chunk_total = s;
        }
        __syncthreads();
        int incl = x + (wid > 0 ? wsum[wid - 1] : 0);
        int excl = carry + incl - v;
        if (i < NNODES) { rptr[i] = excl; cursor[i] = excl; }
        carry += chunk_total;
        __syncthreads();   // protect wsum/chunk_total before next chunk
    }
    if (t == 0) rptr[NNODES] = carry;
}

// ---------------------------------------------------------------------------
// 3. scatter edges into CSR slots
// ---------------------------------------------------------------------------
__global__ void fill_kernel(const int* __restrict__ src, const int* __restrict__ dst,
                            const float* __restrict__ w, int* __restrict__ cursor,
                            int* __restrict__ csrc, float* __restrict__ csrw) {
    int e = blockIdx.x * blockDim.x + threadIdx.x;
    if (e < NEDGES) {
        int d   = dst[e];
        int pos = atomicAdd(&cursor[d], 1);
        csrc[pos] = src[e];
        csrw[pos] = w[e];
    }
}

// ---------------------------------------------------------------------------
// 4. CSR gather spmm: Y[d,:] = sum_e w_e * X[src_e,:]   (one block per node,
//    one thread per feature column, no atomics)
// ---------------------------------------------------------------------------
__global__ void spmm_csr_kernel(const float* __restrict__ X,
                                const int* __restrict__ rptr,
                                const int* __restrict__ cs,
                                const float* __restrict__ cw,
                                float* __restrict__ Y, int F) {
    const int d = blockIdx.x;
    const int t = threadIdx.x;
    const int b = rptr[d], e = rptr[d + 1];
    float acc = 0.0f;
    int i = b;
    for (; i + 4 <= e; i += 4) {
        int   s0 = cs[i], s1 = cs[i + 1], s2 = cs[i + 2], s3 = cs[i + 3];
        float w0 = cw[i], w1 = cw[i + 1], w2 = cw[i + 2], w3 = cw[i + 3];
        float v0 = X[(size_t)s0 * F + t];
        float v1 = X[(size_t)s1 * F + t];
        float v2 = X[(size_t)s2 * F + t];
        float v3 = X[(size_t)s3 * F + t];
        acc = fmaf(w0, v0, acc);
        acc = fmaf(w1, v1, acc);
        acc = fmaf(w2, v2, acc);
        acc = fmaf(w3, v3, acc);
    }
    for (; i < e; i++) acc = fmaf(cw[i], X[(size_t)cs[i] * F + t], acc);
    Y[(size_t)d * F + t] = acc;
}

// ---------------------------------------------------------------------------
// 7. spmm2 fused with bias+relu+global-sum-pool:
//    G[seg[d],:] += relu( sum_e w_e * T[src_e,:] + b2 )
// ---------------------------------------------------------------------------
__global__ void spmm_pool_kernel(const float* __restrict__ T,
                                 const int* __restrict__ rptr,
                                 const int* __restrict__ cs,
                                 const float* __restrict__ cw,
                                 const float* __restrict__ b2,
                                 const int* __restrict__ seg,
                                 float* __restrict__ G) {
    const int d = blockIdx.x;
    const int t = threadIdx.x;
    const int b = rptr[d], e = rptr[d + 1];
    float acc = 0.0f;
    int i = b;
    for (; i + 4 <= e; i += 4) {
        int   s0 = cs[i], s1 = cs[i + 1], s2 = cs[i + 2], s3 = cs[i + 3];
        float w0 = cw[i], w1 = cw[i + 1], w2 = cw[i + 2], w3 = cw[i + 3];
        float v0 = T[(size_t)s0 * HID + t];
        float v1 = T[(size_t)s1 * HID + t];
        float v2 = T[(size_t)s2 * HID + t];
        float v3 = T[(size_t)s3 * HID + t];
        acc = fmaf(w0, v0, acc);
        acc = fmaf(w1, v1, acc);
        acc = fmaf(w2, v2, acc);
        acc = fmaf(w3, v3, acc);
    }
    for (; i < e; i++) acc = fmaf(cw[i], T[(size_t)cs[i] * HID + t], acc);
    float v = fmaxf(acc + b2[t], 0.0f);
    atomicAdd(&G[(size_t)seg[d] * HID + t], v);
}

// ---------------------------------------------------------------------------
// 5/6. tiled SGEMM: C[M,N] = A[M,K] @ B[K,N] (+ bias, relu if fused)
//      128x128 block tile, BK=8, 8x8 per-thread microtile, 256 threads
// ---------------------------------------------------------------------------
template <int FUSE_BIAS_RELU>
__global__ __launch_bounds__(256)
void sgemm_kernel(const float* __restrict__ A, const float* __restrict__ B,
                  const float* __restrict__ bias, float* __restrict__ C,
                  int M, int N, int K) {
    constexpr int BM = 128, BN = 128, BK = 8, TM = 8, TN = 8;
    __shared__ float As[BK][BM];
    __shared__ float Bs[BK][BN];

    const int tid = threadIdx.x;
    const int bm = blockIdx.x * BM, bn = blockIdx.y * BN;
    const int tx = tid & 15, ty = tid >> 4;

    float acc[TM][TN];
    #pragma unroll
    for (int i = 0; i < TM; i++)
        #pragma unroll
        for (int j = 0; j < TN; j++) acc[i][j] = 0.0f;

    const int arow = tid >> 1;           // 0..127
    const int akq  = (tid & 1) * 4;      // 0 or 4
    const int brow = tid >> 5;           // 0..7
    const int bcol = (tid & 31) * 4;     // 0..124

    const float* Aptr = A + (size_t)(bm + arow) * K + akq;
    const bool avalid = (bm + arow) < M;
    const float* Bptr = B + (size_t)brow * N + bn + bcol;

    for (int k0 = 0; k0 < K; k0 += BK) {
        float4 av = avalid ? *(const float4*)(Aptr + k0)
                           : make_float4(0.f, 0.f, 0.f, 0.f);
        As[akq + 0][arow] = av.x;
        As[akq + 1][arow] = av.y;
        As[akq + 2][arow] = av.z;
        As[akq + 3][arow] = av.w;
        float4 bv = *(const float4*)(Bptr + (size_t)k0 * N);
        *(float4*)&Bs[brow][bcol] = bv;
        __syncthreads();

        #pragma unroll
        for (int kk = 0; kk < BK; kk++) {
            float ar[TM], bc[TN];
            #pragma unroll
            for (int i = 0; i < TM; i++) ar[i] = As[kk][ty * TM + i];
            #pragma unroll
            for (int j = 0; j < TN; j++) bc[j] = Bs[kk][tx * TN + j];
            #pragma unroll
            for (int i = 0; i < TM; i++)
                #pragma unroll
                for (int j = 0; j < TN; j++)
                    acc[i][j] = fmaf(ar[i], bc[j], acc[i][j]);
        }
        __syncthreads();
    }

    #pragma unroll
    for (int i = 0; i < TM; i++) {
        int row = bm + ty * TM + i;
        if (row >= M) continue;
        #pragma unroll
        for (int j = 0; j < TN; j += 4) {
            int col = bn + tx * TN + j;
            float4 v;
            v.x = acc[i][j + 0];
            v.y = acc[i][j + 1];
            v.z = acc[i][j + 2];
            v.w = acc[i][j + 3];
            if (FUSE_BIAS_RELU) {
                v.x = fmaxf(v.x + bias[col + 0], 0.0f);
                v.y = fmaxf(v.y + bias[col + 1], 0.0f);
                v.z = fmaxf(v.z + bias[col + 2], 0.0f);
                v.w = fmaxf(v.w + bias[col + 3], 0.0f);
            }
            *(float4*)&C[(size_t)row * N + col] = v;
        }
    }
}

// ---------------------------------------------------------------------------
// 8. dense head: out[b] = relu(G[b]@Wd + bd) @ Wo + bo
// ---------------------------------------------------------------------------
__global__ void head_kernel(const float* __restrict__ G, const float* __restrict__ Wd,
                            const float* __restrict__ bd, const float* __restrict__ Wo,
                            const float* __restrict__ bo, float* __restrict__ out) {
    __shared__ float gs[HID];
    __shared__ float red[HID];
    const int b = blockIdx.x, t = threadIdx.x;
    gs[t] = G[(size_t)b * HID + t];
    __syncthreads();
    float acc = bd[t];
    #pragma unroll 4
    for (int k = 0; k < HID; k++) acc = fmaf(gs[k], Wd[(size_t)k * HID + t], acc);
    acc = fmaxf(acc, 0.0f) * Wo[t];
    red[t] = acc;
    __syncthreads();
    for (int s = HID / 2; s > 0; s >>= 1) {
        if (t < s) red[t] += red[t + s];
        __syncthreads();
    }
    if (t == 0) out[b] = red[0] + bo[0];
}

// ---------------------------------------------------------------------------
// launch
// ---------------------------------------------------------------------------
extern "C" void kernel_launch(void* const* d_in, const int* in_sizes, int n_in,
                              void* d_out, int out_size) {
    const float* x        = (const float*)d_in[0];   // [N,128]
    const int*   edge_src = (const int*)  d_in[1];   // [E]
    const int*   edge_dst = (const int*)  d_in[2];   // [E]
    const float* edge_w   = (const float*)d_in[3];   // [E]
    const int*   seg_ids  = (const int*)  d_in[4];   // [N]
    const float* W1 = (const float*)d_in[5];         // [128,256]
    const float* b1 = (const float*)d_in[6];
    const float* W2 = (const float*)d_in[7];         // [256,256]
    const float* b2 = (const float*)d_in[8];
    const float* Wd = (const float*)d_in[9];         // [256,256]
    const float* bd = (const float*)d_in[10];
    const float* Wo = (const float*)d_in[11];        // [256,1]
    const float* bo = (const float*)d_in[12];
    float* out = (float*)d_out;                      // [128]

    float *pAX, *pH1, *pT2, *pG, *pcsrw;
    int *pdeg, *prptr, *pcursor, *pcsrc;
    cudaGetSymbolAddress((void**)&pAX, d_AX);
    cudaGetSymbolAddress((void**)&pH1, d_H1);
    cudaGetSymbolAddress((void**)&pT2, d_T2);
    cudaGetSymbolAddress((void**)&pG, d_G);
    cudaGetSymbolAddress((void**)&pdeg, d_deg);
    cudaGetSymbolAddress((void**)&prptr, d_rptr);
    cudaGetSymbolAddress((void**)&pcursor, d_cursor);
    cudaGetSymbolAddress((void**)&pcsrc, d_csrc);
    cudaGetSymbolAddress((void**)&pcsrw, d_csrw);

    // 0. zero deg + pooled accumulator
    zero_kernel<<<(NNODES + 255) / 256, 256>>>(pdeg, pG);
    // 1-3. build CSR-by-dst
    hist_kernel<<<(NEDGES + 255) / 256, 256>>>(edge_dst, pdeg);
    scan_kernel<<<1, 1024>>>(pdeg, prptr, pcursor);
    fill_kernel<<<(NEDGES + 255) / 256, 256>>>(edge_src, edge_dst, edge_w,
                                               pcursor, pcsrc, pcsrw);
    // 4. AX = A @ X   (spmm on the 128-wide input: spmm(x@W1) == spmm(x)@W1)
    spmm_csr_kernel<<<NNODES, FIN>>>(x, prptr, pcsrc, pcsrw, pAX, FIN);
    // 5. H1 = relu(AX @ W1 + b1)
    {
        dim3 grid((NNODES + 127) / 128, HID / 128);
        sgemm_kernel<1><<<grid, 256>>>(pAX, W1, b1, pH1, NNODES, HID, FIN);
    }
    // 6. T2 = H1 @ W2
    {
        dim3 grid((NNODES + 127) / 128, HID / 128);
        sgemm_kernel<0><<<grid, 256>>>(pH1, W2, nullptr, pT2, NNODES, HID, HID);
    }
    // 7. G[seg] += relu(spmm(T2) + b2)
    spmm_pool_kernel<<<NNODES, HID>>>(pT2, prptr, pcsrc, pcsrw, b2, seg_ids, pG);
    // 8. head
    head_kernel<<<NGRAPH, HID>>>(pG, Wd, bd, Wo, bo, out);
}

// round 5
// speedup vs baseline: 1.6599x; 1.6599x over previous
#include <cuda_runtime.h>
#include <cuda_bf16.h>
#include <cstdint>

// Problem constants
#define NNODES 50000
#define NEDGES 800000
#define FIN    128
#define HID    256
#define NGRAPH 128

// ---------------------------------------------------------------------------
// Scratch (static __device__ arrays; no allocation allowed)
// ---------------------------------------------------------------------------
__device__ float d_AX[(size_t)NNODES * FIN];       // A @ X            [N,128]
__device__ float d_H1[(size_t)NNODES * HID];       // relu(AX@W1+b1)   [N,256]
__device__ float d_T2[(size_t)NNODES * HID];       // H1 @ W2          [N,256]
__device__ int   d_deg[NNODES];
__device__ int   d_rptr[NNODES + 1];
__device__ int   d_cursor[NNODES];
__device__ int   d_csrc[NEDGES];
__device__ float d_csrw[NEDGES];
__device__ float d_G[NGRAPH * HID];                // pooled graph features

// ---------------------------------------------------------------------------
// 0. zero deg + G
// ---------------------------------------------------------------------------
__global__ void zero_kernel(int* deg, float* G) {
    int i = blockIdx.x * blockDim.x + threadIdx.x;
    if (i < NNODES) deg[i] = 0;
    if (i < NGRAPH * HID) G[i] = 0.0f;
}

// ---------------------------------------------------------------------------
// 1. degree histogram over edge_dst
// ---------------------------------------------------------------------------
__global__ void hist_kernel(const int* __restrict__ dst, int* __restrict__ deg) {
    int e = blockIdx.x * blockDim.x + threadIdx.x;
    if (e < NEDGES) atomicAdd(&deg[dst[e]], 1);
}

// ---------------------------------------------------------------------------
// 2. single-block exclusive scan (shuffle-based), also seeds cursor
// ---------------------------------------------------------------------------
__global__ void scan_kernel(const int* __restrict__ deg, int* __restrict__ rptr,
                            int* __restrict__ cursor) {
    __shared__ int wsum[32];
    __shared__ int chunk_total;
    const int t = threadIdx.x, lane = t & 31, wid = t >> 5;
    int carry = 0;
    for (int base = 0; base < NNODES; base += 1024) {
        int i = base + t;
        int v = (i < NNODES) ? deg[i] : 0;
        int x = v;
        #pragma unroll
        for (int off = 1; off < 32; off <<= 1) {
            int y = __shfl_up_sync(0xffffffffu, x, off);
            if (lane >= off) x += y;
        }
        if (lane == 31) wsum[wid] = x;
        __syncthreads();
        if (wid == 0) {
            int s = wsum[lane];
            #pragma unroll
            for (int off = 1; off < 32; off <<= 1) {
                int y = __shfl_up_sync(0xffffffffu, s, off);
                if (lane >= off) s += y;
            }
            wsum[lane] = s;
            if (lane == 31) chunk_total = s;
        }
        __syncthreads();
        int incl = x + (wid > 0 ? wsum[wid - 1] : 0);
        int excl = carry + incl - v;
        if (i < NNODES) { rptr[i] = excl; cursor[i] = excl; }
        carry += chunk_total;
        __syncthreads();
    }
    if (t == 0) rptr[NNODES] = carry;
}

// ---------------------------------------------------------------------------
// 3. scatter edges into CSR slots
// ---------------------------------------------------------------------------
__global__ void fill_kernel(const int* __restrict__ src, const int* __restrict__ dst,
                            const float* __restrict__ w, int* __restrict__ cursor,
                            int* __restrict__ csrc, float* __restrict__ csrw) {
    int e = blockIdx.x * blockDim.x + threadIdx.x;
    if (e < NEDGES) {
        int d   = dst[e];
        int pos = atomicAdd(&cursor[d], 1);
        csrc[pos] = src[e];
        csrw[pos] = w[e];
    }
}

// ---------------------------------------------------------------------------
// 4. CSR gather spmm, float4 columns: Y[d,:] = sum_e w_e * X[src_e,:]
//    F4 = row width in float4s; 256/F4 nodes per block; no atomics.
// ---------------------------------------------------------------------------
template <int F4>
__global__ __launch_bounds__(256)
void spmm_csr_v4(const float4* __restrict__ X4,
                 const int* __restrict__ rptr,
                 const int* __restrict__ cs,
                 const float* __restrict__ cw,
                 float4* __restrict__ Y4) {
    constexpr int NPB = 256 / F4;
    const int g = threadIdx.x / F4;
    const int c = threadIdx.x % F4;
    const int d = blockIdx.x * NPB + g;
    if (d >= NNODES) return;
    const int b = rptr[d], e = rptr[d + 1];
    float4 acc = make_float4(0.f, 0.f, 0.f, 0.f);
    int i = b;
    for (; i + 4 <= e; i += 4) {
        int   s0 = cs[i], s1 = cs[i + 1], s2 = cs[i + 2], s3 = cs[i + 3];
        float w0 = cw[i], w1 = cw[i + 1], w2 = cw[i + 2], w3 = cw[i + 3];
        float4 v0 = X4[(size_t)s0 * F4 + c];
        float4 v1 = X4[(size_t)s1 * F4 + c];
        float4 v2 = X4[(size_t)s2 * F4 + c];
        float4 v3 = X4[(size_t)s3 * F4 + c];
        acc.x = fmaf(w0, v0.x, acc.x); acc.y = fmaf(w0, v0.y, acc.y);
        acc.z = fmaf(w0, v0.z, acc.z); acc.w = fmaf(w0, v0.w, acc.w);
        acc.x = fmaf(w1, v1.x, acc.x); acc.y = fmaf(w1, v1.y, acc.y);
        acc.z = fmaf(w1, v1.z, acc.z); acc.w = fmaf(w1, v1.w, acc.w);
        acc.x = fmaf(w2, v2.x, acc.x); acc.y = fmaf(w2, v2.y, acc.y);
        acc.z = fmaf(w2, v2.z, acc.z); acc.w = fmaf(w2, v2.w, acc.w);
        acc.x = fmaf(w3, v3.x, acc.x); acc.y = fmaf(w3, v3.y, acc.y);
        acc.z = fmaf(w3, v3.z, acc.z); acc.w = fmaf(w3, v3.w, acc.w);
    }
    for (; i < e; i++) {
        float w0 = cw[i];
        float4 v0 = X4[(size_t)cs[i] * F4 + c];
        acc.x = fmaf(w0, v0.x, acc.x); acc.y = fmaf(w0, v0.y, acc.y);
        acc.z = fmaf(w0, v0.z, acc.z); acc.w = fmaf(w0, v0.w, acc.w);
    }
    Y4[(size_t)d * F4 + c] = acc;
}

// ---------------------------------------------------------------------------
// 7. spmm2 fused with bias+relu+global-sum-pool (float4 gathers):
//    G[seg[d],:] += relu( sum_e w_e * T[src_e,:] + b2 )
// ---------------------------------------------------------------------------
__global__ __launch_bounds__(256)
void spmm_pool_v4(const float4* __restrict__ T4,
                  const int* __restrict__ rptr,
                  const int* __restrict__ cs,
                  const float* __restrict__ cw,
                  const float4* __restrict__ b24,
                  const int* __restrict__ seg,
                  float* __restrict__ G) {
    constexpr int F4 = HID / 4;           // 64
    constexpr int NPB = 256 / F4;         // 4
    const int g = threadIdx.x / F4;
    const int c = threadIdx.x % F4;
    const int d = blockIdx.x * NPB + g;
    if (d >= NNODES) return;
    const int b = rptr[d], e = rptr[d + 1];
    float4 acc = make_float4(0.f, 0.f, 0.f, 0.f);
    int i = b;
    for (; i + 4 <= e; i += 4) {
        int   s0 = cs[i], s1 = cs[i + 1], s2 = cs[i + 2], s3 = cs[i + 3];
        float w0 = cw[i], w1 = cw[i + 1], w2 = cw[i + 2], w3 = cw[i + 3];
        float4 v0 = T4[(size_t)s0 * F4 + c];
        float4 v1 = T4[(size_t)s1 * F4 + c];
        float4 v2 = T4[(size_t)s2 * F4 + c];
        float4 v3 = T4[(size_t)s3 * F4 + c];
        acc.x = fmaf(w0, v0.x, acc.x); acc.y = fmaf(w0, v0.y, acc.y);
        acc.z = fmaf(w0, v0.z, acc.z); acc.w = fmaf(w0, v0.w, acc.w);
        acc.x = fmaf(w1, v1.x, acc.x); acc.y = fmaf(w1, v1.y, acc.y);
        acc.z = fmaf(w1, v1.z, acc.z); acc.w = fmaf(w1, v1.w, acc.w);
        acc.x = fmaf(w2, v2.x, acc.x); acc.y = fmaf(w2, v2.y, acc.y);
        acc.z = fmaf(w2, v2.z, acc.z); acc.w = fmaf(w2, v2.w, acc.w);
        acc.x = fmaf(w3, v3.x, acc.x); acc.y = fmaf(w3, v3.y, acc.y);
        acc.z = fmaf(w3, v3.z, acc.z); acc.w = fmaf(w3, v3.w, acc.w);
    }
    for (; i < e; i++) {
        float w0 = cw[i];
        float4 v0 = T4[(size_t)cs[i] * F4 + c];
        acc.x = fmaf(w0, v0.x, acc.x); acc.y = fmaf(w0, v0.y, acc.y);
        acc.z = fmaf(w0, v0.z, acc.z); acc.w = fmaf(w0, v0.w, acc.w);
    }
    float4 bb = b24[c];
    float r0 = fmaxf(acc.x + bb.x, 0.f);
    float r1 = fmaxf(acc.y + bb.y, 0.f);
    float r2 = fmaxf(acc.z + bb.z, 0.f);
    float r3 = fmaxf(acc.w + bb.w, 0.f);
    float* gp = &G[(size_t)seg[d] * HID + c * 4];
    atomicAdd(gp + 0, r0);
    atomicAdd(gp + 1, r1);
    atomicAdd(gp + 2, r2);
    atomicAdd(gp + 3, r3);
}

// ---------------------------------------------------------------------------
// 5/6. 3xTF32 tensor-core GEMM: C[M,N] = A[M,K] @ B[K,N] (+bias+relu)
//      BM=128 BN=128 BK=32, 8 warps, 64x32 warp tile, mma.m16n8k8
// ---------------------------------------------------------------------------
__device__ __forceinline__ void split_tf32(float x, uint32_t& hi, uint32_t& lo) {
    uint32_t h;
    asm("cvt.rna.tf32.f32 %0, %1;" : "=r"(h) : "f"(x));
    float r = x - __uint_as_float(h);
    uint32_t l;
    asm("cvt.rna.tf32.f32 %0, %1;" : "=r"(l) : "f"(r));
    hi = h; lo = l;
}

__device__ __forceinline__ void mma8(float* c, const uint32_t* a, const uint32_t* b) {
    asm volatile(
        "mma.sync.aligned.m16n8k8.row.col.f32.tf32.tf32.f32 "
        "{%0,%1,%2,%3},{%4,%5,%6,%7},{%8,%9},{%0,%1,%2,%3};"
        : "+f"(c[0]), "+f"(c[1]), "+f"(c[2]), "+f"(c[3])
        : "r"(a[0]), "r"(a[1]), "r"(a[2]), "r"(a[3]), "r"(b[0]), "r"(b[1]));
}

template <int FUSE_BIAS_RELU>
__global__ __launch_bounds__(256, 1)
void tf32_gemm_kernel(const float* __restrict__ A, const float* __restrict__ B,
                      const float* __restrict__ bias, float* __restrict__ C,
                      int M, int N, int K) {
    constexpr int BM = 128, BN = 128, BK = 32;
    __shared__ float As[BM][BK + 4];   // bank-conflict-free for frag loads
    __shared__ float Bs[BK][BN + 8];

    const int tid  = threadIdx.x;
    const int lane = tid & 31;
    const int warp = tid >> 5;
    const int wm = warp >> 2;          // 0..1  (64-row slab)
    const int wn = warp & 3;           // 0..3  (32-col slab)
    const int gr = lane >> 2;          // 0..7
    const int gc = lane & 3;           // 0..3
    const int bm = blockIdx.x * BM;
    const int bn = blockIdx.y * BN;

    float acc[4][4][4];
    #pragma unroll
    for (int mi = 0; mi < 4; mi++)
        #pragma unroll
        for (int ni = 0; ni < 4; ni++)
            #pragma unroll
            for (int r = 0; r < 4; r++) acc[mi][ni][r] = 0.0f;

    const int nTiles = K / BK;

    // global-load addressing: A tile = 1024 float4 (4/thread), B tile = same
    float4 aReg[4], bReg[4];
    #pragma unroll
    for (int i = 0; i < 4; i++) {
        int idx  = tid + i * 256;
        int arow = idx >> 3, akq = (idx & 7) * 4;
        aReg[i] = (bm + arow < M)
                    ? *(const float4*)(A + (size_t)(bm + arow) * K + akq)
                    : make_float4(0.f, 0.f, 0.f, 0.f);
        int brow = idx >> 5, bcol = (idx & 31) * 4;
        bReg[i] = *(const float4*)(B + (size_t)brow * N + bn + bcol);
    }

    for (int kt = 0; kt < nTiles; kt++) {
        __syncthreads();
        #pragma unroll
        for (int i = 0; i < 4; i++) {
            int idx  = tid + i * 256;
            int arow = idx >> 3, akq = (idx & 7) * 4;
            *(float4*)&As[arow][akq] = aReg[i];
            int brow = idx >> 5, bcol = (idx & 31) * 4;
            Bs[brow][bcol + 0] = bReg[i].x;
            Bs[brow][bcol + 1] = bReg[i].y;
            Bs[brow][bcol + 2] = bReg[i].z;
            Bs[brow][bcol + 3] = bReg[i].w;
        }
        __syncthreads();

        // prefetch next tile while computing
        if (kt + 1 < nTiles) {
            int k0n = (kt + 1) * BK;
            #pragma unroll
            for (int i = 0; i < 4; i++) {
                int idx  = tid + i * 256;
                int arow = idx >> 3, akq = (idx & 7) * 4;
                aReg[i] = (bm + arow < M)
                            ? *(const float4*)(A + (size_t)(bm + arow) * K + k0n + akq)
                            : make_float4(0.f, 0.f, 0.f, 0.f);
                int brow = idx >> 5, bcol = (idx & 31) * 4;
                bReg[i] = *(const float4*)(B + (size_t)(k0n + brow) * N + bn + bcol);
            }
        }

        #pragma unroll
        for (int ks = 0; ks < 4; ks++) {
            uint32_t ahi[4][4], alo[4][4], bhi[4][2], blo[4][2];
            const int k = ks * 8 + gc;
            #pragma unroll
            for (int mi = 0; mi < 4; mi++) {
                int r = wm * 64 + mi * 16 + gr;
                split_tf32(As[r][k],         ahi[mi][0], alo[mi][0]);
                split_tf32(As[r + 8][k],     ahi[mi][1], alo[mi][1]);
                split_tf32(As[r][k + 4],     ahi[mi][2], alo[mi][2]);
                split_tf32(As[r + 8][k + 4], ahi[mi][3], alo[mi][3]);
            }
            #pragma unroll
            for (int ni = 0; ni < 4; ni++) {
                int col = wn * 32 + ni * 8 + gr;
                split_tf32(Bs[k][col],     bhi[ni][0], blo[ni][0]);
                split_tf32(Bs[k + 4][col], bhi[ni][1], blo[ni][1]);
            }
            #pragma unroll
            for (int mi = 0; mi < 4; mi++)
                #pragma unroll
                for (int ni = 0; ni < 4; ni++) {
                    mma8(acc[mi][ni], ahi[mi], bhi[ni]);
                    mma8(acc[mi][ni], ahi[mi], blo[ni]);
                    mma8(acc[mi][ni], alo[mi], bhi[ni]);
                }
        }
    }

    // epilogue
    #pragma unroll
    for (int mi = 0; mi < 4; mi++) {
        int row0 = bm + wm * 64 + mi * 16 + gr;
        int row1 = row0 + 8;
        #pragma unroll
        for (int ni = 0; ni < 4; ni++) {
            int col = bn + wn * 32 + ni * 8 + gc * 2;
            float v0 = acc[mi][ni][0], v1 = acc[mi][ni][1];
            float v2 = acc[mi][ni][2], v3 = acc[mi][ni][3];
            if (FUSE_BIAS_RELU) {
                float bb0 = bias[col], bb1 = bias[col + 1];
                v0 = fmaxf(v0 + bb0, 0.f); v1 = fmaxf(v1 + bb1, 0.f);
                v2 = fmaxf(v2 + bb0, 0.f); v3 = fmaxf(v3 + bb1, 0.f);
            }
            if (row0 < M) { float2 s = {v0, v1}; *(float2*)&C[(size_t)row0 * N + col] = s; }
            if (row1 < M) { float2 s = {v2, v3}; *(float2*)&C[(size_t)row1 * N + col] = s; }
        }
    }
}

// ---------------------------------------------------------------------------
// 8. dense head: out[b] = relu(G[b]@Wd + bd) @ Wo + bo
// ---------------------------------------------------------------------------
__global__ void head_kernel(const float* __restrict__ G, const float* __restrict__ Wd,
                            const float* __restrict__ bd, const float* __restrict__ Wo,
                            const float* __restrict__ bo, float* __restrict__ out) {
    __shared__ float gs[HID];
    __shared__ float red[HID];
    const int b = blockIdx.x, t = threadIdx.x;
    gs[t] = G[(size_t)b * HID + t];
    __syncthreads();
    float acc = bd[t];
    #pragma unroll 4
    for (int k = 0; k < HID; k++) acc = fmaf(gs[k], Wd[(size_t)k * HID + t], acc);
    acc = fmaxf(acc, 0.0f) * Wo[t];
    red[t] = acc;
    __syncthreads();
    for (int s = HID / 2; s > 0; s >>= 1) {
        if (t < s) red[t] += red[t + s];
        __syncthreads();
    }
    if (t == 0) out[b] = red[0] + bo[0];
}

// ---------------------------------------------------------------------------
// launch
// ---------------------------------------------------------------------------
extern "C" void kernel_launch(void* const* d_in, const int* in_sizes, int n_in,
                              void* d_out, int out_size) {
    const float* x        = (const float*)d_in[0];   // [N,128]
    const int*   edge_src = (const int*)  d_in[1];   // [E]
    const int*   edge_dst = (const int*)  d_in[2];   // [E]
    const float* edge_w   = (const float*)d_in[3];   // [E]
    const int*   seg_ids  = (const int*)  d_in[4];   // [N]
    const float* W1 = (const float*)d_in[5];         // [128,256]
    const float* b1 = (const float*)d_in[6];
    const float* W2 = (const float*)d_in[7];         // [256,256]
    const float* b2 = (const float*)d_in[8];
    const float* Wd = (const float*)d_in[9];         // [256,256]
    const float* bd = (const float*)d_in[10];
    const float* Wo = (const float*)d_in[11];        // [256,1]
    const float* bo = (const float*)d_in[12];
    float* out = (float*)d_out;                      // [128]

    float *pAX, *pH1, *pT2, *pG, *pcsrw;
    int *pdeg, *prptr, *pcursor, *pcsrc;
    cudaGetSymbolAddress((void**)&pAX, d_AX);
    cudaGetSymbolAddress((void**)&pH1, d_H1);
    cudaGetSymbolAddress((void**)&pT2, d_T2);
    cudaGetSymbolAddress((void**)&pG, d_G);
    cudaGetSymbolAddress((void**)&pdeg, d_deg);
    cudaGetSymbolAddress((void**)&prptr, d_rptr);
    cudaGetSymbolAddress((void**)&pcursor, d_cursor);
    cudaGetSymbolAddress((void**)&pcsrc, d_csrc);
    cudaGetSymbolAddress((void**)&pcsrw, d_csrw);

    // 0. zero deg + pooled accumulator
    zero_kernel<<<(NNODES + 255) / 256, 256>>>(pdeg, pG);
    // 1-3. build CSR-by-dst
    hist_kernel<<<(NEDGES + 255) / 256, 256>>>(edge_dst, pdeg);
    scan_kernel<<<1, 1024>>>(pdeg, prptr, pcursor);
    fill_kernel<<<(NEDGES + 255) / 256, 256>>>(edge_src, edge_dst, edge_w,
                                               pcursor, pcsrc, pcsrw);
    // 4. AX = A @ X   (spmm on the 128-wide input: spmm(x@W1) == spmm(x)@W1)
    {
        constexpr int NPB = 256 / (FIN / 4);   // 8 nodes / block
        spmm_csr_v4<FIN / 4><<<(NNODES + NPB - 1) / NPB, 256>>>(
            (const float4*)x, prptr, pcsrc, pcsrw, (float4*)pAX);
    }
    // 5. H1 = relu(AX @ W1 + b1)   [3xTF32 tensor cores]
    {
        dim3 grid((NNODES + 127) / 128, HID / 128);
        tf32_gemm_kernel<1><<<grid, 256>>>(pAX, W1, b1, pH1, NNODES, HID, FIN);
    }
    // 6. T2 = H1 @ W2              [3xTF32 tensor cores]
    {
        dim3 grid((NNODES + 127) / 128, HID / 128);
        tf32_gemm_kernel<0><<<grid, 256>>>(pH1, W2, nullptr, pT2, NNODES, HID, HID);
    }
    // 7. G[seg] += relu(spmm(T2) + b2)
    {
        constexpr int NPB = 256 / (HID / 4);   // 4 nodes / block
        spmm_pool_v4<<<(NNODES + NPB - 1) / NPB, 256>>>(
            (const float4*)pT2, prptr, pcsrc, pcsrw, (const float4*)b2, seg_ids, pG);
    }
    // 8. head
    head_kernel<<<NGRAPH, HID>>>(pG, Wd, bd, Wo, bo, out);
}

// round 6
// speedup vs baseline: 1.9943x; 1.2014x over previous
#include <cuda_runtime.h>
#include <cuda_bf16.h>
#include <cstdint>

// Problem constants
#define NNODES 50000
#define NEDGES 800000
#define FIN    128
#define HID    256
#define NGRAPH 128

// ---------------------------------------------------------------------------
// Scratch (static __device__ arrays; no allocation allowed)
// ---------------------------------------------------------------------------
__device__ float d_AX[(size_t)NNODES * FIN];       // A @ X            [N,128]
__device__ float d_H1[(size_t)NNODES * HID];       // relu(AX@W1+b1)   [N,256]
__device__ float d_T2[(size_t)NNODES * HID];       // H1 @ W2          [N,256]
__device__ int   d_deg[NNODES];
__device__ int   d_rptr[NNODES + 1];
__device__ int   d_cursor[NNODES];
__device__ int   d_csrc[NEDGES];
__device__ float d_csrw[NEDGES];
__device__ float d_G[NGRAPH * HID];                // pooled graph features

// ---------------------------------------------------------------------------
// 0. zero deg + G
// ---------------------------------------------------------------------------
__global__ void zero_kernel(int* deg, float* G) {
    int i = blockIdx.x * blockDim.x + threadIdx.x;
    if (i < NNODES) deg[i] = 0;
    if (i < NGRAPH * HID) G[i] = 0.0f;
}

// ---------------------------------------------------------------------------
// 1. degree histogram over edge_dst
// ---------------------------------------------------------------------------
__global__ void hist_kernel(const int* __restrict__ dst, int* __restrict__ deg) {
    int e = blockIdx.x * blockDim.x + threadIdx.x;
    if (e < NEDGES) atomicAdd(&deg[dst[e]], 1);
}

// ---------------------------------------------------------------------------
// 2. single-block exclusive scan (shuffle-based), also seeds cursor
// ---------------------------------------------------------------------------
__global__ void scan_kernel(const int* __restrict__ deg, int* __restrict__ rptr,
                            int* __restrict__ cursor) {
    __shared__ int wsum[32];
    __shared__ int chunk_total;
    const int t = threadIdx.x, lane = t & 31, wid = t >> 5;
    int carry = 0;
    for (int base = 0; base < NNODES; base += 1024) {
        int i = base + t;
        int v = (i < NNODES) ? deg[i] : 0;
        int x = v;
        #pragma unroll
        for (int off = 1; off < 32; off <<= 1) {
            int y = __shfl_up_sync(0xffffffffu, x, off);
            if (lane >= off) x += y;
        }
        if (lane == 31) wsum[wid] = x;
        __syncthreads();
        if (wid == 0) {
            int s = wsum[lane];
            #pragma unroll
            for (int off = 1; off < 32; off <<= 1) {
                int y = __shfl_up_sync(0xffffffffu, s, off);
                if (lane >= off) s += y;
            }
            wsum[lane] = s;
            if (lane == 31) chunk_total = s;
        }
        __syncthreads();
        int incl = x + (wid > 0 ? wsum[wid - 1] : 0);
        int excl = carry + incl - v;
        if (i < NNODES) { rptr[i] = excl; cursor[i] = excl; }
        carry += chunk_total;
        __syncthreads();
    }
    if (t == 0) rptr[NNODES] = carry;
}

// ---------------------------------------------------------------------------
// 3. scatter edges into CSR slots
// ---------------------------------------------------------------------------
__global__ void fill_kernel(const int* __restrict__ src, const int* __restrict__ dst,
                            const float* __restrict__ w, int* __restrict__ cursor,
                            int* __restrict__ csrc, float* __restrict__ csrw) {
    int e = blockIdx.x * blockDim.x + threadIdx.x;
    if (e < NEDGES) {
        int d   = dst[e];
        int pos = atomicAdd(&cursor[d], 1);
        csrc[pos] = src[e];
        csrw[pos] = w[e];
    }
}

// ---------------------------------------------------------------------------
// 4. CSR gather spmm, float4 columns: Y[d,:] = sum_e w_e * X[src_e,:]
// ---------------------------------------------------------------------------
template <int F4>
__global__ __launch_bounds__(256)
void spmm_csr_v4(const float4* __restrict__ X4,
                 const int* __restrict__ rptr,
                 const int* __restrict__ cs,
                 const float* __restrict__ cw,
                 float4* __restrict__ Y4) {
    constexpr int NPB = 256 / F4;
    const int g = threadIdx.x / F4;
    const int c = threadIdx.x % F4;
    const int d = blockIdx.x * NPB + g;
    if (d >= NNODES) return;
    const int b = rptr[d], e = rptr[d + 1];
    float4 acc = make_float4(0.f, 0.f, 0.f, 0.f);
    int i = b;
    for (; i + 4 <= e; i += 4) {
        int   s0 = cs[i], s1 = cs[i + 1], s2 = cs[i + 2], s3 = cs[i + 3];
        float w0 = cw[i], w1 = cw[i + 1], w2 = cw[i + 2], w3 = cw[i + 3];
        float4 v0 = X4[(size_t)s0 * F4 + c];
        float4 v1 = X4[(size_t)s1 * F4 + c];
        float4 v2 = X4[(size_t)s2 * F4 + c];
        float4 v3 = X4[(size_t)s3 * F4 + c];
        acc.x = fmaf(w0, v0.x, acc.x); acc.y = fmaf(w0, v0.y, acc.y);
        acc.z = fmaf(w0, v0.z, acc.z); acc.w = fmaf(w0, v0.w, acc.w);
        acc.x = fmaf(w1, v1.x, acc.x); acc.y = fmaf(w1, v1.y, acc.y);
        acc.z = fmaf(w1, v1.z, acc.z); acc.w = fmaf(w1, v1.w, acc.w);
        acc.x = fmaf(w2, v2.x, acc.x); acc.y = fmaf(w2, v2.y, acc.y);
        acc.z = fmaf(w2, v2.z, acc.z); acc.w = fmaf(w2, v2.w, acc.w);
        acc.x = fmaf(w3, v3.x, acc.x); acc.y = fmaf(w3, v3.y, acc.y);
        acc.z = fmaf(w3, v3.z, acc.z); acc.w = fmaf(w3, v3.w, acc.w);
    }
    for (; i < e; i++) {
        float w0 = cw[i];
        float4 v0 = X4[(size_t)cs[i] * F4 + c];
        acc.x = fmaf(w0, v0.x, acc.x); acc.y = fmaf(w0, v0.y, acc.y);
        acc.z = fmaf(w0, v0.z, acc.z); acc.w = fmaf(w0, v0.w, acc.w);
    }
    Y4[(size_t)d * F4 + c] = acc;
}

// ---------------------------------------------------------------------------
// 7. spmm2 fused with bias+relu+global-sum-pool (float4 gathers)
// ---------------------------------------------------------------------------
__global__ __launch_bounds__(256)
void spmm_pool_v4(const float4* __restrict__ T4,
                  const int* __restrict__ rptr,
                  const int* __restrict__ cs,
                  const float* __restrict__ cw,
                  const float4* __restrict__ b24,
                  const int* __restrict__ seg,
                  float* __restrict__ G) {
    constexpr int F4 = HID / 4;           // 64
    constexpr int NPB = 256 / F4;         // 4
    const int g = threadIdx.x / F4;
    const int c = threadIdx.x % F4;
    const int d = blockIdx.x * NPB + g;
    if (d >= NNODES) return;
    const int b = rptr[d], e = rptr[d + 1];
    float4 acc = make_float4(0.f, 0.f, 0.f, 0.f);
    int i = b;
    for (; i + 4 <= e; i += 4) {
        int   s0 = cs[i], s1 = cs[i + 1], s2 = cs[i + 2], s3 = cs[i + 3];
        float w0 = cw[i], w1 = cw[i + 1], w2 = cw[i + 2], w3 = cw[i + 3];
        float4 v0 = T4[(size_t)s0 * F4 + c];
        float4 v1 = T4[(size_t)s1 * F4 + c];
        float4 v2 = T4[(size_t)s2 * F4 + c];
        float4 v3 = T4[(size_t)s3 * F4 + c];
        acc.x = fmaf(w0, v0.x, acc.x); acc.y = fmaf(w0, v0.y, acc.y);
        acc.z = fmaf(w0, v0.z, acc.z); acc.w = fmaf(w0, v0.w, acc.w);
        acc.x = fmaf(w1, v1.x, acc.x); acc.y = fmaf(w1, v1.y, acc.y);
        acc.z = fmaf(w1, v1.z, acc.z); acc.w = fmaf(w1, v1.w, acc.w);
        acc.x = fmaf(w2, v2.x, acc.x); acc.y = fmaf(w2, v2.y, acc.y);
        acc.z = fmaf(w2, v2.z, acc.z); acc.w = fmaf(w2, v2.w, acc.w);
        acc.x = fmaf(w3, v3.x, acc.x); acc.y = fmaf(w3, v3.y, acc.y);
        acc.z = fmaf(w3, v3.z, acc.z); acc.w = fmaf(w3, v3.w, acc.w);
    }
    for (; i < e; i++) {
        float w0 = cw[i];
        float4 v0 = T4[(size_t)cs[i] * F4 + c];
        acc.x = fmaf(w0, v0.x, acc.x); acc.y = fmaf(w0, v0.y, acc.y);
        acc.z = fmaf(w0, v0.z, acc.z); acc.w = fmaf(w0, v0.w, acc.w);
    }
    float4 bb = b24[c];
    float r0 = fmaxf(acc.x + bb.x, 0.f);
    float r1 = fmaxf(acc.y + bb.y, 0.f);
    float r2 = fmaxf(acc.z + bb.z, 0.f);
    float r3 = fmaxf(acc.w + bb.w, 0.f);
    float* gp = &G[(size_t)seg[d] * HID + c * 4];
    atomicAdd(gp + 0, r0);
    atomicAdd(gp + 1, r1);
    atomicAdd(gp + 2, r2);
    atomicAdd(gp + 3, r3);
}

// ---------------------------------------------------------------------------
// 5/6. 3-term bf16-split tensor-core GEMM: C = A @ B (+bias+relu)
//      BM=128 BN=128 BK=32, 8 warps, 64x32 warp tile, mma.m16n8k16.bf16
//      Split done ONCE at smem staging; fragments via ldmatrix.
// ---------------------------------------------------------------------------
__device__ __forceinline__ void ldsm_x4(uint32_t& r0, uint32_t& r1,
                                        uint32_t& r2, uint32_t& r3, uint32_t a) {
    asm volatile("ldmatrix.sync.aligned.m8n8.x4.shared.b16 {%0,%1,%2,%3},[%4];"
                 : "=r"(r0), "=r"(r1), "=r"(r2), "=r"(r3) : "r"(a));
}
__device__ __forceinline__ void ldsm_x2t(uint32_t& r0, uint32_t& r1, uint32_t a) {
    asm volatile("ldmatrix.sync.aligned.m8n8.x2.trans.shared.b16 {%0,%1},[%2];"
                 : "=r"(r0), "=r"(r1) : "r"(a));
}
__device__ __forceinline__ void mma16(float* c, const uint32_t* a, const uint32_t* b) {
    asm volatile(
        "mma.sync.aligned.m16n8k16.row.col.f32.bf16.bf16.f32 "
        "{%0,%1,%2,%3},{%4,%5,%6,%7},{%8,%9},{%0,%1,%2,%3};"
        : "+f"(c[0]), "+f"(c[1]), "+f"(c[2]), "+f"(c[3])
        : "r"(a[0]), "r"(a[1]), "r"(a[2]), "r"(a[3]), "r"(b[0]), "r"(b[1]));
}
__device__ __forceinline__ __nv_bfloat162 split_pair_hi(float x, float y) {
    return __nv_bfloat162(__float2bfloat16(x), __float2bfloat16(y));
}
__device__ __forceinline__ __nv_bfloat162 split_pair_lo(float x, float y) {
    __nv_bfloat16 hx = __float2bfloat16(x), hy = __float2bfloat16(y);
    return __nv_bfloat162(__float2bfloat16(x - __bfloat162float(hx)),
                          __float2bfloat16(y - __bfloat162float(hy)));
}

template <int FUSE_BIAS_RELU>
__global__ __launch_bounds__(256, 1)
void bf16x3_gemm_kernel(const float* __restrict__ A, const float* __restrict__ B,
                        const float* __restrict__ bias, float* __restrict__ C,
                        int M, int N, int K) {
    constexpr int BM = 128, BN = 128, BK = 32;
    constexpr int AKS = BK + 8;    // 40 bf16 row stride (conflict-free ldmatrix)
    constexpr int BKS = BN + 8;    // 136 bf16 row stride

    __shared__ __nv_bfloat16 sAhi[BM * AKS];
    __shared__ __nv_bfloat16 sAlo[BM * AKS];
    __shared__ __nv_bfloat16 sBhi[BK * BKS];
    __shared__ __nv_bfloat16 sBlo[BK * BKS];

    const int tid  = threadIdx.x;
    const int lane = tid & 31;
    const int warp = tid >> 5;
    const int wm = warp >> 2;          // 0..1  (64-row slab)
    const int wn = warp & 3;           // 0..3  (32-col slab)
    const int gr = lane >> 2;          // 0..7
    const int gc = lane & 3;           // 0..3
    const int bm = blockIdx.x * BM;
    const int bn = blockIdx.y * BN;

    const uint32_t uAhi = (uint32_t)__cvta_generic_to_shared(sAhi);
    const uint32_t uAlo = (uint32_t)__cvta_generic_to_shared(sAlo);
    const uint32_t uBhi = (uint32_t)__cvta_generic_to_shared(sBhi);
    const uint32_t uBlo = (uint32_t)__cvta_generic_to_shared(sBlo);

    // per-thread ldmatrix lane addressing
    const int a_row_l = wm * 64 + ((lane >> 3) & 1) * 8 + (lane & 7); // + mi*16
    const int a_k_l   = (lane >> 4) * 8;                              // + ks*16
    const int b_k_l   = (lane & 7) + ((lane >> 3) & 1) * 8;           // + ks*16

    float acc[4][4][4];
    #pragma unroll
    for (int mi = 0; mi < 4; mi++)
        #pragma unroll
        for (int ni = 0; ni < 4; ni++)
            #pragma unroll
            for (int r = 0; r < 4; r++) acc[mi][ni][r] = 0.0f;

    const int nTiles = K / BK;

    float4 aReg[4], bReg[4];
    #pragma unroll
    for (int i = 0; i < 4; i++) {
        int idx  = tid + i * 256;
        int arow = idx >> 3, akq = (idx & 7) * 4;
        aReg[i] = (bm + arow < M)
                    ? *(const float4*)(A + (size_t)(bm + arow) * K + akq)
                    : make_float4(0.f, 0.f, 0.f, 0.f);
        int brow = idx >> 5, bcol = (idx & 31) * 4;
        bReg[i] = *(const float4*)(B + (size_t)brow * N + bn + bcol);
    }

    for (int kt = 0; kt < nTiles; kt++) {
        __syncthreads();
        #pragma unroll
        for (int i = 0; i < 4; i++) {
            int idx  = tid + i * 256;
            int arow = idx >> 3, akq = (idx & 7) * 4;
            int ao = arow * AKS + akq;
            *(__nv_bfloat162*)&sAhi[ao]     = split_pair_hi(aReg[i].x, aReg[i].y);
            *(__nv_bfloat162*)&sAhi[ao + 2] = split_pair_hi(aReg[i].z, aReg[i].w);
            *(__nv_bfloat162*)&sAlo[ao]     = split_pair_lo(aReg[i].x, aReg[i].y);
            *(__nv_bfloat162*)&sAlo[ao + 2] = split_pair_lo(aReg[i].z, aReg[i].w);
            int brow = idx >> 5, bcol = (idx & 31) * 4;
            int bo = brow * BKS + bcol;
            *(__nv_bfloat162*)&sBhi[bo]     = split_pair_hi(bReg[i].x, bReg[i].y);
            *(__nv_bfloat162*)&sBhi[bo + 2] = split_pair_hi(bReg[i].z, bReg[i].w);
            *(__nv_bfloat162*)&sBlo[bo]     = split_pair_lo(bReg[i].x, bReg[i].y);
            *(__nv_bfloat162*)&sBlo[bo + 2] = split_pair_lo(bReg[i].z, bReg[i].w);
        }
        __syncthreads();

        if (kt + 1 < nTiles) {
            int k0n = (kt + 1) * BK;
            #pragma unroll
            for (int i = 0; i < 4; i++) {
                int idx  = tid + i * 256;
                int arow = idx >> 3, akq = (idx & 7) * 4;
                aReg[i] = (bm + arow < M)
                            ? *(const float4*)(A + (size_t)(bm + arow) * K + k0n + akq)
                            : make_float4(0.f, 0.f, 0.f, 0.f);
                int brow = idx >> 5, bcol = (idx & 31) * 4;
                bReg[i] = *(const float4*)(B + (size_t)(k0n + brow) * N + bn + bcol);
            }
        }

        #pragma unroll
        for (int ks = 0; ks < 2; ks++) {
            uint32_t ahi[4][4], alo[4][4], bhi[4][2], blo[4][2];
            #pragma unroll
            for (int mi = 0; mi < 4; mi++) {
                uint32_t off = (uint32_t)(((a_row_l + mi * 16) * AKS +
                                           ks * 16 + a_k_l) * 2);
                ldsm_x4(ahi[mi][0], ahi[mi][1], ahi[mi][2], ahi[mi][3], uAhi + off);
                ldsm_x4(alo[mi][0], alo[mi][1], alo[mi][2], alo[mi][3], uAlo + off);
            }
            #pragma unroll
            for (int ni = 0; ni < 4; ni++) {
                uint32_t off = (uint32_t)(((ks * 16 + b_k_l) * BKS +
                                           wn * 32 + ni * 8) * 2);
                ldsm_x2t(bhi[ni][0], bhi[ni][1], uBhi + off);
                ldsm_x2t(blo[ni][0], blo[ni][1], uBlo + off);
            }
            #pragma unroll
            for (int mi = 0; mi < 4; mi++)
                #pragma unroll
                for (int ni = 0; ni < 4; ni++) {
                    mma16(acc[mi][ni], ahi[mi], bhi[ni]);
                    mma16(acc[mi][ni], ahi[mi], blo[ni]);
                    mma16(acc[mi][ni], alo[mi], bhi[ni]);
                }
        }
    }

    // epilogue (D layout: c0=(gr,2gc) c1=(gr,2gc+1) c2=(gr+8,2gc) c3=(gr+8,2gc+1))
    #pragma unroll
    for (int mi = 0; mi < 4; mi++) {
        int row0 = bm + wm * 64 + mi * 16 + gr;
        int row1 = row0 + 8;
        #pragma unroll
        for (int ni = 0; ni < 4; ni++) {
            int col = bn + wn * 32 + ni * 8 + gc * 2;
            float v0 = acc[mi][ni][0], v1 = acc[mi][ni][1];
            float v2 = acc[mi][ni][2], v3 = acc[mi][ni][3];
            if (FUSE_BIAS_RELU) {
                float bb0 = bias[col], bb1 = bias[col + 1];
                v0 = fmaxf(v0 + bb0, 0.f); v1 = fmaxf(v1 + bb1, 0.f);
                v2 = fmaxf(v2 + bb0, 0.f); v3 = fmaxf(v3 + bb1, 0.f);
            }
            if (row0 < M) { float2 s = {v0, v1}; *(float2*)&C[(size_t)row0 * N + col] = s; }
            if (row1 < M) { float2 s = {v2, v3}; *(float2*)&C[(size_t)row1 * N + col] = s; }
        }
    }
}

// ---------------------------------------------------------------------------
// 8. dense head: out[b] = relu(G[b]@Wd + bd) @ Wo + bo
// ---------------------------------------------------------------------------
__global__ void head_kernel(const float* __restrict__ G, const float* __restrict__ Wd,
                            const float* __restrict__ bd, const float* __restrict__ Wo,
                            const float* __restrict__ bo, float* __restrict__ out) {
    __shared__ float gs[HID];
    __shared__ float red[HID];
    const int b = blockIdx.x, t = threadIdx.x;
    gs[t] = G[(size_t)b * HID + t];
    __syncthreads();
    float acc = bd[t];
    #pragma unroll 4
    for (int k = 0; k < HID; k++) acc = fmaf(gs[k], Wd[(size_t)k * HID + t], acc);
    acc = fmaxf(acc, 0.0f) * Wo[t];
    red[t] = acc;
    __syncthreads();
    for (int s = HID / 2; s > 0; s >>= 1) {
        if (t < s) red[t] += red[t + s];
        __syncthreads();
    }
    if (t == 0) out[b] = red[0] + bo[0];
}

// ---------------------------------------------------------------------------
// launch
// ---------------------------------------------------------------------------
extern "C" void kernel_launch(void* const* d_in, const int* in_sizes, int n_in,
                              void* d_out, int out_size) {
    const float* x        = (const float*)d_in[0];   // [N,128]
    const int*   edge_src = (const int*)  d_in[1];   // [E]
    const int*   edge_dst = (const int*)  d_in[2];   // [E]
    const float* edge_w   = (const float*)d_in[3];   // [E]
    const int*   seg_ids  = (const int*)  d_in[4];   // [N]
    const float* W1 = (const float*)d_in[5];         // [128,256]
    const float* b1 = (const float*)d_in[6];
    const float* W2 = (const float*)d_in[7];         // [256,256]
    const float* b2 = (const float*)d_in[8];
    const float* Wd = (const float*)d_in[9];         // [256,256]
    const float* bd = (const float*)d_in[10];
    const float* Wo = (const float*)d_in[11];        // [256,1]
    const float* bo = (const float*)d_in[12];
    float* out = (float*)d_out;                      // [128]

    float *pAX, *pH1, *pT2, *pG, *pcsrw;
    int *pdeg, *prptr, *pcursor, *pcsrc;
    cudaGetSymbolAddress((void**)&pAX, d_AX);
    cudaGetSymbolAddress((void**)&pH1, d_H1);
    cudaGetSymbolAddress((void**)&pT2, d_T2);
    cudaGetSymbolAddress((void**)&pG, d_G);
    cudaGetSymbolAddress((void**)&pdeg, d_deg);
    cudaGetSymbolAddress((void**)&prptr, d_rptr);
    cudaGetSymbolAddress((void**)&pcursor, d_cursor);
    cudaGetSymbolAddress((void**)&pcsrc, d_csrc);
    cudaGetSymbolAddress((void**)&pcsrw, d_csrw);

    // 0. zero deg + pooled accumulator
    zero_kernel<<<(NNODES + 255) / 256, 256>>>(pdeg, pG);
    // 1-3. build CSR-by-dst
    hist_kernel<<<(NEDGES + 255) / 256, 256>>>(edge_dst, pdeg);
    scan_kernel<<<1, 1024>>>(pdeg, prptr, pcursor);
    fill_kernel<<<(NEDGES + 255) / 256, 256>>>(edge_src, edge_dst, edge_w,
                                               pcursor, pcsrc, pcsrw);
    // 4. AX = A @ X   (spmm on the 128-wide input: spmm(x@W1) == spmm(x)@W1)
    {
        constexpr int NPB = 256 / (FIN / 4);   // 8 nodes / block
        spmm_csr_v4<FIN / 4><<<(NNODES + NPB - 1) / NPB, 256>>>(
            (const float4*)x, prptr, pcsrc, pcsrw, (float4*)pAX);
    }
    // 5. H1 = relu(AX @ W1 + b1)   [bf16x3 tensor cores]
    {
        dim3 grid((NNODES + 127) / 128, HID / 128);
        bf16x3_gemm_kernel<1><<<grid, 256>>>(pAX, W1, b1, pH1, NNODES, HID, FIN);
    }
    // 6. T2 = H1 @ W2              [bf16x3 tensor cores]
    {
        dim3 grid((NNODES + 127) / 128, HID / 128);
        bf16x3_gemm_kernel<0><<<grid, 256>>>(pH1, W2, nullptr, pT2, NNODES, HID, HID);
    }
    // 7. G[seg] += relu(spmm(T2) + b2)
    {
        constexpr int NPB = 256 / (HID / 4);   // 4 nodes / block
        spmm_pool_v4<<<(NNODES + NPB - 1) / NPB, 256>>>(
            (const float4*)pT2, prptr, pcsrc, pcsrw, (const float4*)b2, seg_ids, pG);
    }
    // 8. head
    head_kernel<<<NGRAPH, HID>>>(pG, Wd, bd, Wo, bo, out);
}